// round 13
// baseline (speedup 1.0000x reference)
#include <cuda_runtime.h>

// Depthwise conv_transpose2d(stride=4, k=7, bilinear) == separable x4 upsample.
// Input  x: [4, 256, 64, 64] fp32, Output: [4, 256, 259, 259] fp32.
//
// out[o] = wA*in[cell-1] + (1-wA)*in[cell], wA = 0.75-0.25*(o&3), OOB taps = 0.
//
// Row alignment phase hds(4a+py) = (py - plane) & 3 is constant per
// (plane, py): each output row = hds head scalars + 64 aligned float4
// chunks + (3-hds) tail scalars, decided at compile time via the plane&3
// template. Every chunk store is an aligned STG.128.
//
// R13 change vs R11/R12: 128-thread blocks. B300 maps warp wid%4 -> SMSP;
// the previous 64-thread blocks (2 warps) only ever occupied SMSP 0/1,
// idling half the SM's schedulers + LSU dispatch. Now each block carries
// 4 warps (all 4 SMSPs): 2 y-groups per block, grid 2 x 1024 = 2048
// blocks = 13.8/SM, single wave at 14 blocks/SM (56 warps, regs<=36).

namespace {
constexpr int H = 64, W = 64;
constexpr int OH = 259, OW = 259;
constexpr int PLANES = 4 * 256;   // 1024
}

template <int PM>   // plane & 3
__device__ __forceinline__ void run_group(
    const float* __restrict__ xp, float* __restrict__ op,
    int j, int b0, int b1)
{
    const bool c0ok = (j >= 1);
    const bool c2ok = (j < 63);

    auto load3 = [&](int r, float& t0, float& t1, float& t2) {
        t0 = 0.f; t1 = 0.f; t2 = 0.f;
        if ((unsigned)r < (unsigned)H) {
            const float* row = xp + r * W;
            t0 = c0ok ? __ldg(row + j - 1) : 0.f;
            t1 = __ldg(row + j);
            t2 = c2ok ? __ldg(row + j + 1) : 0.f;
        }
    };

    auto doRow = [&](float* rowOut, float wy, int hds,
                     float dA0, float dA1, float dA2,
                     float B0, float B1, float B2) {
        float v0 = fmaf(wy, dA0, B0);
        float v1 = fmaf(wy, dA1, B1);
        float v2 = fmaf(wy, dA2, B2);
        float d0 = v0 - v1, d1 = v1 - v2;
        float4 o;
        if (hds == 0)
            o = make_float4(fmaf(0.75f,d0,v1), fmaf(0.50f,d0,v1), fmaf(0.25f,d0,v1), v1);
        else if (hds == 1)
            o = make_float4(fmaf(0.50f,d0,v1), fmaf(0.25f,d0,v1), v1, fmaf(0.75f,d1,v2));
        else if (hds == 2)
            o = make_float4(fmaf(0.25f,d0,v1), v1, fmaf(0.75f,d1,v2), fmaf(0.50f,d1,v2));
        else
            o = make_float4(v1, fmaf(0.75f,d1,v2), fmaf(0.50f,d1,v2), fmaf(0.25f,d1,v2));
        *reinterpret_cast<float4*>(rowOut + hds + 4 * j) = o;

        if (j == 0) {            // head scalars ox = 0..hds-1
#pragma unroll
            for (int s = 0; s < 3; s++)
                if (s < hds) rowOut[s] = fmaf(0.75f - 0.25f * s, d0, v1);
        } else if (j == 63) {    // tail scalars ox = 256+u, u = hds..2
#pragma unroll
            for (int u = 0; u < 3; u++)
                if (u >= hds) rowOut[256 + u] = fmaf(0.75f - 0.25f * u, d1, v2);
        }
    };

    constexpr int h0 = (0 - PM) & 3, h1 = (1 - PM) & 3;
    constexpr int h2 = (2 - PM) & 3, h3 = (3 - PM) & 3;

    float A0,A1,A2, B0,B1,B2, N0,N1,N2;
    load3(b0 - 1, A0, A1, A2);
    load3(b0,     B0, B1, B2);
    load3(b0 + 1, N0, N1, N2);

    float* r0 = op + (size_t)(4 * b0) * OW;   // accumulated row pointer

#pragma unroll 1
    for (int a = b0; a < b1; a++) {
        float P0, P1, P2;
        load3(a + 2, P0, P1, P2);             // consumed 2 blocks later
        float dA0 = A0 - B0, dA1 = A1 - B1, dA2 = A2 - B2;
        doRow(r0,          0.75f, h0, dA0, dA1, dA2, B0, B1, B2);
        doRow(r0 + OW,     0.50f, h1, dA0, dA1, dA2, B0, B1, B2);
        doRow(r0 + 2 * OW, 0.25f, h2, dA0, dA1, dA2, B0, B1, B2);
        if (a < 64)
            doRow(r0 + 3 * OW, 0.0f, h3, dA0, dA1, dA2, B0, B1, B2);
        A0 = B0; A1 = B1; A2 = B2;
        B0 = N0; B1 = N1; B2 = N2;
        N0 = P0; N1 = P1; N2 = P2;
        r0 += 4 * OW;
    }
}

__global__ void __launch_bounds__(128, 14)
bilinear_up4_smsp_kernel(const float* __restrict__ x, float* __restrict__ out) {
    int j = threadIdx.x & 63;                  // chunk / cell index 0..63
    int g = 2 * blockIdx.x + (threadIdx.x >> 6);  // y-group 0..3
    int plane = blockIdx.y;

    const float* xp = x + plane * (H * W);
    float* op = out + (size_t)plane * ((size_t)OH * OW);

    // y-block ranges per group: {0..16, 17..32, 33..48, 49..64}
    int b0 = (g == 0) ? 0 : (g == 1) ? 17 : (g == 2) ? 33 : 49;
    int b1 = (g == 0) ? 17 : (g == 1) ? 33 : (g == 2) ? 49 : 65;

    switch (plane & 3) {
        case 0:  run_group<0>(xp, op, j, b0, b1); break;
        case 1:  run_group<1>(xp, op, j, b0, b1); break;
        case 2:  run_group<2>(xp, op, j, b0, b1); break;
        default: run_group<3>(xp, op, j, b0, b1); break;
    }
}

extern "C" void kernel_launch(void* const* d_in, const int* in_sizes, int n_in,
                              void* d_out, int out_size) {
    const float* x = (const float*)d_in[0];
    float* out = (float*)d_out;
    (void)in_sizes; (void)n_in; (void)out_size;

    dim3 grid(2, PLANES);              // 2048 blocks x 128 threads, one wave
    bilinear_up4_smsp_kernel<<<grid, 128>>>(x, out);
}

// round 14
// speedup vs baseline: 1.1309x; 1.1309x over previous
#include <cuda_runtime.h>

// Depthwise conv_transpose2d(stride=4, k=7, bilinear) == separable x4 upsample.
// Input  x: [4, 256, 64, 64] fp32, Output: [4, 256, 259, 259] fp32.
//
// out[o] = wA*in[cell-1] + (1-wA)*in[cell], wA = 0.75-0.25*(o&3), OOB taps = 0.
//
// Row alignment phase hds(4a+py) = (py - plane) & 3 is constant per
// (plane, py): each output row = hds head scalars + 64 aligned float4
// chunks + (3-hds) tail scalars, decided at compile time via the plane&3
// template. Every chunk store is an aligned STG.128.
//
// R14 change vs R11: fine-grained multi-wave scheduling. Single-wave
// launches stall at achieved-occ ~60% because per-CTA runtime spread
// (cross-CTA L1tex queue contention, B300_MICROARCH "Multi-CTA spread")
// leaves straggler gaps with no fill work. Now each block does a uniform
// slice of 5 y-blocks (65 = 13 x 5): grid 13 x 1024 = 13312 blocks of 64
// threads, ~2.8 waves at 32 blocks/SM -> work stealing absorbs spread.

namespace {
constexpr int H = 64, W = 64;
constexpr int OH = 259, OW = 259;
constexpr int PLANES = 4 * 256;   // 1024
constexpr int SLICE = 5;          // y-blocks per block
constexpr int NSLICES = 13;       // 13 * 5 = 65
}

template <int PM>   // plane & 3
__device__ __forceinline__ void run_group(
    const float* __restrict__ xp, float* __restrict__ op,
    int j, int b0, int b1)
{
    const bool c0ok = (j >= 1);
    const bool c2ok = (j < 63);

    auto load3 = [&](int r, float& t0, float& t1, float& t2) {
        t0 = 0.f; t1 = 0.f; t2 = 0.f;
        if ((unsigned)r < (unsigned)H) {
            const float* row = xp + r * W;
            t0 = c0ok ? __ldg(row + j - 1) : 0.f;
            t1 = __ldg(row + j);
            t2 = c2ok ? __ldg(row + j + 1) : 0.f;
        }
    };

    auto doRow = [&](float* rowOut, float wy, int hds,
                     float dA0, float dA1, float dA2,
                     float B0, float B1, float B2) {
        float v0 = fmaf(wy, dA0, B0);
        float v1 = fmaf(wy, dA1, B1);
        float v2 = fmaf(wy, dA2, B2);
        float d0 = v0 - v1, d1 = v1 - v2;
        float4 o;
        if (hds == 0)
            o = make_float4(fmaf(0.75f,d0,v1), fmaf(0.50f,d0,v1), fmaf(0.25f,d0,v1), v1);
        else if (hds == 1)
            o = make_float4(fmaf(0.50f,d0,v1), fmaf(0.25f,d0,v1), v1, fmaf(0.75f,d1,v2));
        else if (hds == 2)
            o = make_float4(fmaf(0.25f,d0,v1), v1, fmaf(0.75f,d1,v2), fmaf(0.50f,d1,v2));
        else
            o = make_float4(v1, fmaf(0.75f,d1,v2), fmaf(0.50f,d1,v2), fmaf(0.25f,d1,v2));
        *reinterpret_cast<float4*>(rowOut + hds + 4 * j) = o;

        if (j == 0) {            // head scalars ox = 0..hds-1
#pragma unroll
            for (int s = 0; s < 3; s++)
                if (s < hds) rowOut[s] = fmaf(0.75f - 0.25f * s, d0, v1);
        } else if (j == 63) {    // tail scalars ox = 256+u, u = hds..2
#pragma unroll
            for (int u = 0; u < 3; u++)
                if (u >= hds) rowOut[256 + u] = fmaf(0.75f - 0.25f * u, d1, v2);
        }
    };

    constexpr int h0 = (0 - PM) & 3, h1 = (1 - PM) & 3;
    constexpr int h2 = (2 - PM) & 3, h3 = (3 - PM) & 3;

    float A0,A1,A2, B0,B1,B2, N0,N1,N2;
    load3(b0 - 1, A0, A1, A2);
    load3(b0,     B0, B1, B2);
    load3(b0 + 1, N0, N1, N2);

    float* r0 = op + (size_t)(4 * b0) * OW;   // accumulated row pointer

#pragma unroll 1
    for (int a = b0; a < b1; a++) {
        float P0, P1, P2;
        load3(a + 2, P0, P1, P2);             // consumed 2 blocks later
        float dA0 = A0 - B0, dA1 = A1 - B1, dA2 = A2 - B2;
        doRow(r0,          0.75f, h0, dA0, dA1, dA2, B0, B1, B2);
        doRow(r0 + OW,     0.50f, h1, dA0, dA1, dA2, B0, B1, B2);
        doRow(r0 + 2 * OW, 0.25f, h2, dA0, dA1, dA2, B0, B1, B2);
        if (a < 64)
            doRow(r0 + 3 * OW, 0.0f, h3, dA0, dA1, dA2, B0, B1, B2);
        A0 = B0; A1 = B1; A2 = B2;
        B0 = N0; B1 = N1; B2 = N2;
        N0 = P0; N1 = P1; N2 = P2;
        r0 += 4 * OW;
    }
}

__global__ void __launch_bounds__(64, 32)
bilinear_up4_slice_kernel(const float* __restrict__ x, float* __restrict__ out) {
    int j = threadIdx.x;               // chunk / cell index 0..63
    int slice = blockIdx.x;            // 0..12
    int plane = blockIdx.y;

    const float* xp = x + plane * (H * W);
    float* op = out + (size_t)plane * ((size_t)OH * OW);

    int b0 = slice * SLICE;
    int b1 = b0 + SLICE;               // uniform 5 y-blocks per block

    switch (plane & 3) {
        case 0:  run_group<0>(xp, op, j, b0, b1); break;
        case 1:  run_group<1>(xp, op, j, b0, b1); break;
        case 2:  run_group<2>(xp, op, j, b0, b1); break;
        default: run_group<3>(xp, op, j, b0, b1); break;
    }
}

extern "C" void kernel_launch(void* const* d_in, const int* in_sizes, int n_in,
                              void* d_out, int out_size) {
    const float* x = (const float*)d_in[0];
    float* out = (float*)d_out;
    (void)in_sizes; (void)n_in; (void)out_size;

    dim3 grid(NSLICES, PLANES);        // 13312 blocks x 64 threads, ~2.8 waves
    bilinear_up4_slice_kernel<<<grid, 64>>>(x, out);
}

// round 15
// speedup vs baseline: 1.1316x; 1.0006x over previous
#include <cuda_runtime.h>

// Depthwise conv_transpose2d(stride=4, k=7, bilinear) == separable x4 upsample.
// Input  x: [4, 256, 64, 64] fp32, Output: [4, 256, 259, 259] fp32.
//
// out[o] = wA*in[cell-1] + (1-wA)*in[cell], wA = 0.75-0.25*(o&3), OOB taps = 0.
//
// Row alignment phase hds(4a+py) = (py - plane) & 3 is constant per
// (plane, py): each output row = hds head scalars + 64 aligned float4
// chunks + (3-hds) tail scalars, decided at compile time via the plane&3
// template. Every chunk store is an aligned STG.128.
//
// R15 change vs R14: shuffle-based neighbor exchange for loads. Instead of
// 3 scalar LDG per thread per input row (two of them line-splitting), each
// thread loads only c = row[j] (1 coalesced 128B-aligned LDG per warp) and
// warp-boundary lanes 0/31 load one extra neighbor scalar into e. The
// (j-1, j, j+1) triple is reconstructed with __shfl_up/down AT CONSUMPTION
// time, so raw values stay in the 2-deep load pipeline and LDG latency
// stays hidden. L1 load wavefronts per warp-row: ~6 -> 2.
// Schedule unchanged from R14: 13 slices x 5 y-blocks, 64-thread blocks.

namespace {
constexpr int H = 64, W = 64;
constexpr int OH = 259, OW = 259;
constexpr int PLANES = 4 * 256;   // 1024
constexpr int SLICE = 5;          // y-blocks per block
constexpr int NSLICES = 13;       // 13 * 5 = 65
}

template <int PM>   // plane & 3
__device__ __forceinline__ void run_group(
    const float* __restrict__ xp, float* __restrict__ op,
    int j, int b0, int b1)
{
    const int lane = j & 31;
    const bool edgeLane = (lane == 0) || (lane == 31);
    const int jn = j + ((lane == 0) ? -1 : 1);        // neighbor this lane fetches
    const bool eOk = edgeLane && ((unsigned)jn < (unsigned)W);

    // raw row load: center value + boundary-lane neighbor (both pipelined)
    auto loadRaw = [&](int r, float& c, float& e) {
        c = 0.f; e = 0.f;
        if ((unsigned)r < (unsigned)H) {
            const float* row = xp + r * W;
            c = __ldg(row + j);                       // coalesced, 128B-aligned
            if (eOk) e = __ldg(row + jn);             // lanes 0/31 only
        }
    };

    // reconstruct (t0,t1,t2) = row[j-1], row[j], row[j+1] via warp shuffles
    auto expand = [&](float c, float e, float& t0, float& t1, float& t2) {
        t1 = c;
        t0 = __shfl_up_sync(0xffffffffu, c, 1);
        if (lane == 0) t0 = (j == 0) ? 0.f : e;       // cross-warp / left edge
        t2 = __shfl_down_sync(0xffffffffu, c, 1);
        if (lane == 31) t2 = (j == 63) ? 0.f : e;     // cross-warp / right edge
    };

    auto doRow = [&](float* rowOut, float wy, int hds,
                     float dA0, float dA1, float dA2,
                     float B0, float B1, float B2) {
        float v0 = fmaf(wy, dA0, B0);
        float v1 = fmaf(wy, dA1, B1);
        float v2 = fmaf(wy, dA2, B2);
        float d0 = v0 - v1, d1 = v1 - v2;
        float4 o;
        if (hds == 0)
            o = make_float4(fmaf(0.75f,d0,v1), fmaf(0.50f,d0,v1), fmaf(0.25f,d0,v1), v1);
        else if (hds == 1)
            o = make_float4(fmaf(0.50f,d0,v1), fmaf(0.25f,d0,v1), v1, fmaf(0.75f,d1,v2));
        else if (hds == 2)
            o = make_float4(fmaf(0.25f,d0,v1), v1, fmaf(0.75f,d1,v2), fmaf(0.50f,d1,v2));
        else
            o = make_float4(v1, fmaf(0.75f,d1,v2), fmaf(0.50f,d1,v2), fmaf(0.25f,d1,v2));
        *reinterpret_cast<float4*>(rowOut + hds + 4 * j) = o;

        if (j == 0) {            // head scalars ox = 0..hds-1
#pragma unroll
            for (int s = 0; s < 3; s++)
                if (s < hds) rowOut[s] = fmaf(0.75f - 0.25f * s, d0, v1);
        } else if (j == 63) {    // tail scalars ox = 256+u, u = hds..2
#pragma unroll
            for (int u = 0; u < 3; u++)
                if (u >= hds) rowOut[256 + u] = fmaf(0.75f - 0.25f * u, d1, v2);
        }
    };

    constexpr int h0 = (0 - PM) & 3, h1 = (1 - PM) & 3;
    constexpr int h2 = (2 - PM) & 3, h3 = (3 - PM) & 3;

    // preamble: expand rows b0-1, b0; keep rows b0+1, b0+2 raw in flight
    float cA, eA, cB, eB, cN, eN;
    loadRaw(b0 - 1, cA, eA);
    loadRaw(b0,     cB, eB);
    loadRaw(b0 + 1, cN, eN);

    float A0, A1, A2, B0, B1, B2;
    expand(cA, eA, A0, A1, A2);
    expand(cB, eB, B0, B1, B2);

    float* r0 = op + (size_t)(4 * b0) * OW;   // accumulated row pointer

#pragma unroll 1
    for (int a = b0; a < b1; a++) {
        float cP, eP;
        loadRaw(a + 2, cP, eP);               // consumed 2 iterations later

        float dA0 = A0 - B0, dA1 = A1 - B1, dA2 = A2 - B2;
        doRow(r0,          0.75f, h0, dA0, dA1, dA2, B0, B1, B2);
        doRow(r0 + OW,     0.50f, h1, dA0, dA1, dA2, B0, B1, B2);
        doRow(r0 + 2 * OW, 0.25f, h2, dA0, dA1, dA2, B0, B1, B2);
        if (a < 64)
            doRow(r0 + 3 * OW, 0.0f, h3, dA0, dA1, dA2, B0, B1, B2);

        // rotate: expanded B -> A, expand raw N -> B, raw P -> N
        A0 = B0; A1 = B1; A2 = B2;
        expand(cN, eN, B0, B1, B2);
        cN = cP; eN = eP;
        r0 += 4 * OW;
    }
}

__global__ void __launch_bounds__(64, 28)
bilinear_up4_shfl_kernel(const float* __restrict__ x, float* __restrict__ out) {
    int j = threadIdx.x;               // chunk / cell index 0..63
    int slice = blockIdx.x;            // 0..12
    int plane = blockIdx.y;

    const float* xp = x + plane * (H * W);
    float* op = out + (size_t)plane * ((size_t)OH * OW);

    int b0 = slice * SLICE;
    int b1 = b0 + SLICE;               // uniform 5 y-blocks per block

    switch (plane & 3) {
        case 0:  run_group<0>(xp, op, j, b0, b1); break;
        case 1:  run_group<1>(xp, op, j, b0, b1); break;
        case 2:  run_group<2>(xp, op, j, b0, b1); break;
        default: run_group<3>(xp, op, j, b0, b1); break;
    }
}

extern "C" void kernel_launch(void* const* d_in, const int* in_sizes, int n_in,
                              void* d_out, int out_size) {
    const float* x = (const float*)d_in[0];
    float* out = (float*)d_out;
    (void)in_sizes; (void)n_in; (void)out_size;

    dim3 grid(NSLICES, PLANES);        // 13312 blocks x 64 threads, ~3 waves
    bilinear_up4_shfl_kernel<<<grid, 64>>>(x, out);
}